// round 8
// baseline (speedup 1.0000x reference)
#include <cuda_runtime.h>

// RadiosityPropagater — N=4096, 64 tail lights, 3 bounces.
//  bounce1: sparse gather over 64 light columns (B0 zero elsewhere), fused combine -> g_B.
//  pass:    full O(N^2) recompute gather, packed f32x2 math, 2 receivers/thread.
//           Run twice (bounce 2 from B1, bounce 3 from B2). No F matrix stored.
//  combine: unrolled 32-split reduce; bounce-2 flavor -> g_B, final flavor -> relu(out).
// Deterministic: no float atomics anywhere.

#define NMAX    4096
#define NLIGHTS 64
#define BLK     256
#define JT2     128
#define JS2     (NMAX / JT2)       // 32 j-splits per pass
#define FSCALE  1024.0f
#define INV_S   (1.0f / 1024.0f)

typedef unsigned long long ull;

__device__ float g_part[JS2 * NMAX * 3];       // per-split partial gathers
__device__ float g_B[NMAX * 3];                // radiosity between bounces

__device__ __forceinline__ float frcp(float x) {
    float r; asm("rcp.approx.ftz.f32 %0, %1;" : "=f"(r) : "f"(x)); return r;
}
__device__ __forceinline__ ull pk(float lo, float hi) {
    ull r; asm("mov.b64 %0, {%1, %2};" : "=l"(r) : "f"(lo), "f"(hi)); return r;
}
__device__ __forceinline__ ull sp(float x) {
    ull r; asm("mov.b64 %0, {%1, %1};" : "=l"(r) : "f"(x)); return r;
}
__device__ __forceinline__ void upk(ull v, float& lo, float& hi) {
    asm("mov.b64 {%0, %1}, %2;" : "=f"(lo), "=f"(hi) : "l"(v));
}
__device__ __forceinline__ ull f2fma(ull a, ull b, ull c) {
    ull d; asm("fma.rn.f32x2 %0, %1, %2, %3;" : "=l"(d) : "l"(a), "l"(b), "l"(c)); return d;
}
__device__ __forceinline__ ull f2mul(ull a, ull b) {
    ull d; asm("mul.rn.f32x2 %0, %1, %2;" : "=l"(d) : "l"(a), "l"(b)); return d;
}
__device__ __forceinline__ ull f2add(ull a, ull b) {
    ull d; asm("add.rn.f32x2 %0, %1, %2;" : "=l"(d) : "l"(a), "l"(b)); return d;
}

__device__ __forceinline__ float snf_scale(const float* s, const float* g,
                                           const float* nf, int j) {
    return s[3*j] * s[3*j+1] * g[j] * nf[j] * FSCALE;
}

// ---------------------------------------------------------------- bounce 1
__global__ void __launch_bounds__(BLK) bounce1_kernel(
        const float* __restrict__ means,  const float* __restrict__ geo,
        const float* __restrict__ scales, const float* __restrict__ normals,
        const float* __restrict__ nf,     const float* __restrict__ emis,
        const float* __restrict__ brdf,   int N) {
    __shared__ float4 sM[NLIGHTS];
    __shared__ float4 sS[NLIGHTS];
    __shared__ float  sC[NLIGHTS];
    int tid = threadIdx.x;
    if (tid < NLIGHTS) {
        int jg = N - NLIGHTS + tid;
        float a = snf_scale(scales, geo, nf, jg);
        sM[tid] = make_float4(means[3*jg], means[3*jg+1], means[3*jg+2],
                              emis[3*jg] * INV_S);
        sS[tid] = make_float4(normals[3*jg] * a, normals[3*jg+1] * a,
                              normals[3*jg+2] * a, emis[3*jg+1] * INV_S);
        sC[tid] = emis[3*jg+2] * INV_S;
    }
    __syncthreads();

    int i = blockIdx.x * BLK + tid;
    float rx = means[3*i],   ry = means[3*i+1],   rz = means[3*i+2];
    float nx = normals[3*i], ny = normals[3*i+1], nz = normals[3*i+2];
    float a0 = 0.f, a1 = 0.f, a2 = 0.f;
    #pragma unroll 8
    for (int j = 0; j < NLIGHTS; j++) {
        float4 M = sM[j]; float4 S = sS[j]; float c = sC[j];
        float dx = M.x - rx, dy = M.y - ry, dz = M.z - rz;
        float d2 = fmaf(dx, dx, fmaf(dy, dy, fmaf(dz, dz, 1e-8f)));
        float r  = frcp(d2);
        float rf = r * fminf(fmaxf(r, 1e-4f), 1.0f);
        float pi_ = fmaxf(fmaf(dx, nx,  fmaf(dy, ny,  dz * nz)),  0.f);
        float pj_ = fmaxf(-fmaf(dx, S.x, fmaf(dy, S.y, dz * S.z)), 0.f);
        float w = pi_ * (pj_ * rf);
        a0 = fmaf(w, M.w, a0); a1 = fmaf(w, S.w, a1); a2 = fmaf(w, c, a2);
    }
    bool light = (i >= N - NLIGHTS);
    float e0 = emis[3*i], e1 = emis[3*i+1], e2 = emis[3*i+2];
    g_B[3*i]   = light ? e0 : fmaf(brdf[3*i],   a0, e0);
    g_B[3*i+1] = light ? e1 : fmaf(brdf[3*i+1], a1, e1);
    g_B[3*i+2] = light ? e2 : fmaf(brdf[3*i+2], a2, e2);
}

// ----------------------------------------------- full O(N^2) recompute pass
// Two adjacent receivers per thread, f32x2 packed geometry and w-chain.
// Reads radiosity from g_B, writes per-j-split partial gathers. No F store.
__global__ void __launch_bounds__(BLK) pass_kernel(
        const float* __restrict__ means,  const float* __restrict__ geo,
        const float* __restrict__ scales, const float* __restrict__ normals,
        const float* __restrict__ nf,     int N) {
    __shared__ ulonglong2 sPa[JT2];   // (Mx, My) splatted
    __shared__ ulonglong2 sPb[JT2];   // (Mz, b0') splatted
    __shared__ ulonglong2 sSa[JT2];   // (Sx, Sy) splatted  (scaled normal)
    __shared__ ulonglong2 sSb[JT2];   // (Sz, b1') splatted
    __shared__ ull        sCp[JT2];   // b2' splatted

    int tid = threadIdx.x;
    int j0  = blockIdx.y * JT2;
    for (int j = tid; j < JT2; j += BLK) {
        int jg = j0 + j;
        float a = snf_scale(scales, geo, nf, jg);
        sPa[j] = make_ulonglong2(sp(means[3*jg]), sp(means[3*jg+1]));
        sPb[j] = make_ulonglong2(sp(means[3*jg+2]), sp(g_B[3*jg] * INV_S));
        sSa[j] = make_ulonglong2(sp(normals[3*jg] * a), sp(normals[3*jg+1] * a));
        sSb[j] = make_ulonglong2(sp(normals[3*jg+2] * a), sp(g_B[3*jg+1] * INV_S));
        sCp[j] = sp(g_B[3*jg+2] * INV_S);
    }
    __syncthreads();

    int i0 = blockIdx.x * (BLK * 2) + 2 * tid;
    ull nrx = pk(-means[3*i0],   -means[3*i0+3]);
    ull nry = pk(-means[3*i0+1], -means[3*i0+4]);
    ull nrz = pk(-means[3*i0+2], -means[3*i0+5]);
    ull nxp = pk(normals[3*i0],   normals[3*i0+3]);
    ull nyp = pk(normals[3*i0+1], normals[3*i0+4]);
    ull nzp = pk(normals[3*i0+2], normals[3*i0+5]);
    const ull epsp = sp(1e-8f);

    ull a0p = 0ull, a1p = 0ull, a2p = 0ull;

    #pragma unroll 4
    for (int j = 0; j < JT2; j++) {
        ulonglong2 Pa = sPa[j], Pb = sPb[j];
        ulonglong2 Sa = sSa[j], Sb = sSb[j];
        ull cp = sCp[j];

        ull dxp = f2add(Pa.x, nrx);
        ull dyp = f2add(Pa.y, nry);
        ull dzp = f2add(Pb.x, nrz);
        ull d2p = f2fma(dxp, dxp, f2fma(dyp, dyp, f2fma(dzp, dzp, epsp)));
        ull pip = f2fma(dxp, nxp,  f2fma(dyp, nyp,  f2mul(dzp, nzp)));
        ull pjp = f2fma(dxp, Sa.x, f2fma(dyp, Sa.y, f2mul(dzp, Sb.x)));

        float d20, d21; upk(d2p, d20, d21);
        float r0 = frcp(d20), r1 = frcp(d21);
        float cl0 = fminf(fmaxf(r0, 1e-4f), 1.0f);
        float cl1 = fminf(fmaxf(r1, 1e-4f), 1.0f);
        float pi0, pi1; upk(pip, pi0, pi1);
        float pj0, pj1; upk(pjp, pj0, pj1);

        ull pic = pk(fmaxf(pi0, 0.f),  fmaxf(pi1, 0.f));
        ull pjc = pk(fmaxf(-pj0, 0.f), fmaxf(-pj1, 0.f));
        ull rfp = f2mul(pk(r0, r1), pk(cl0, cl1));
        ull wp  = f2mul(f2mul(pic, pjc), rfp);

        a0p = f2fma(wp, Pb.y, a0p);
        a1p = f2fma(wp, Sb.y, a1p);
        a2p = f2fma(wp, cp,  a2p);
    }

    float a00, a10, a01, a11, a02, a12;
    upk(a0p, a00, a10); upk(a1p, a01, a11); upk(a2p, a02, a12);
    float* p = g_part + (size_t)blockIdx.y * NMAX * 3;
    p[3*i0]   = a00; p[3*i0+1] = a01; p[3*i0+2] = a02;
    p[3*i0+3] = a10; p[3*i0+4] = a11; p[3*i0+5] = a12;
}

// ------------------------------------- combine (unrolled 32-split reduce)
template<int FINAL>
__global__ void __launch_bounds__(BLK) combine_kernel(
        const float* __restrict__ emis, const float* __restrict__ brdf,
        int N, float* __restrict__ out) {
    int idx = blockIdx.x * BLK + threadIdx.x;   // 0 .. 3N-1
    float g = 0.f;
    #pragma unroll
    for (int s = 0; s < JS2; s++)
        g += g_part[(size_t)s * NMAX * 3 + idx];
    bool light = (idx >= 3 * (N - NLIGHTS));
    float e = emis[idx];
    float b = light ? e : fmaf(brdf[idx], g, e);
    if (FINAL) out[idx] = fmaxf(b, 0.f);
    else       g_B[idx] = b;
}

extern "C" void kernel_launch(void* const* d_in, const int* in_sizes, int n_in,
                              void* d_out, int out_size) {
    const float* means   = (const float*)d_in[0];
    const float* geo     = (const float*)d_in[1];
    const float* scales  = (const float*)d_in[2];
    // d_in[3] = rots — unused (API parity only, per reference)
    const float* normals = (const float*)d_in[4];
    const float* nf      = (const float*)d_in[5];
    const float* emis    = (const float*)d_in[6];
    const float* brdf    = (const float*)d_in[7];
    float* out = (float*)d_out;

    int N = in_sizes[1];              // 4096
    int nIB = (N + BLK - 1) / BLK;    // 16
    dim3 pgrid(N / (BLK * 2), JS2);   // (8, 32)

    // Bounce 1 (sparse over tail lights, combine fused) -> g_B
    bounce1_kernel<<<nIB, BLK>>>(means, geo, scales, normals, nf, emis, brdf, N);

    // Bounce 2: full recompute pass + combine -> g_B
    pass_kernel<<<pgrid, BLK>>>(means, geo, scales, normals, nf, N);
    combine_kernel<0><<<(N * 3) / BLK, BLK>>>(emis, brdf, N, out);

    // Bounce 3: full recompute pass + final combine (relu) -> d_out
    pass_kernel<<<pgrid, BLK>>>(means, geo, scales, normals, nf, N);
    combine_kernel<1><<<(N * 3) / BLK, BLK>>>(emis, brdf, N, out);
}